// round 10
// baseline (speedup 1.0000x reference)
#include <cuda_runtime.h>
#include <cuda_fp16.h>

#define HW    160
#define NIMG  32
#define NBITS 128
#define SW    168
#define SW2   (SW / 2)         // 84 pair-entries per row
#define TH    16
#define TROWS 22
#define TILEN (TROWS * SW)     // 3696 column indices
#define PAIRS (TILEN / 2)      // 1848 u64 entries per parity tile
#define BITG  32
#define NTHR  160
#define RR    4                // rows per thread (160 thr = 40 cgs x 4 rgs)

struct __align__(16) BitH {
    __half2 fx1, fx2, B1, A1, B2n, A2n, c;   // 28 B
    int off1, off2;                           // y1*SW + x1 per interp
    int pad;                                  // -> 40 B
};

__device__ __forceinline__ __half2 hfma2_sat(__half2 a, __half2 b, __half2 c) {
    __half2 r;
    asm("fma.rn.sat.f16x2 %0, %1, %2, %3;"
        : "=r"(*(unsigned*)&r)
        : "r"(*(unsigned*)&a), "r"(*(unsigned*)&b), "r"(*(unsigned*)&c));
    return r;
}

__device__ __forceinline__ void stcs128(float4* p, float4 v) {
    asm volatile("st.global.cs.v4.f32 [%0], {%1, %2, %3, %4};"
                 :: "l"(p), "f"(v.x), "f"(v.y), "f"(v.z), "f"(v.w) : "memory");
}

// ---------------------------------------------------------------------------
// Single fused kernel. Block = (16-row tile, 32-bit group, image), 160 thr =
// 40 column-groups (4 cols) x 4 row-groups (4 rows each).
// Delta pair-tiles (u64 entries, halves): EA[j]=(p[2j],p[2j+1],d[2j],d[2j+1]),
// EB[j]= same at s=2j+1, d[s]=p[s+1]-p[s] precomputed at fill. Per interp-row
// a thread loads entries j and j+1 (two dense aligned LDS.64) covering its 4
// columns; horizontal lerp = one HFMA2 each. All loads of a bit batch up
// front (MLP), then a 4-row combine of pure FMA + one STG.128 per row with
// the evict-first (.cs) streaming hint — the output is write-once.
// ---------------------------------------------------------------------------
__global__ __launch_bounds__(NTHR) void fern_main(const float* __restrict__ x,
                                                  const float* __restrict__ dx1,
                                                  const float* __restrict__ dx2,
                                                  const float* __restrict__ dy1,
                                                  const float* __restrict__ dy2,
                                                  const float* __restrict__ th,
                                                  float* __restrict__ out) {
    __shared__ __align__(16) uint2 EA[PAIRS];
    __shared__ __align__(16) uint2 EB[PAIRS];
    __shared__ BitH  sp[BITG];
    __shared__ float wred[4];

    int tid = threadIdx.x;
    int h0  = blockIdx.x * TH;
    int bg  = blockIdx.y;
    int n   = blockIdx.z;

    // --- L = max|offset| (warp reductions; identical in every block) -------
    float m = 0.0f;
    if (tid < 128) {
        m = fmaxf(fmaxf(fabsf(dx1[tid]), fabsf(dx2[tid])),
                  fmaxf(fabsf(dy1[tid]), fabsf(dy2[tid])));
    }
#pragma unroll
    for (int o = 16; o; o >>= 1) m = fmaxf(m, __shfl_xor_sync(0xffffffffu, m, o));
    if (tid < 128 && (tid & 31) == 0) wred[tid >> 5] = m;

    // --- fill delta pair-tiles (one thread builds EA[j] and EB[j]) ---------
    const float* src = x + ((size_t)n * 3 + 1) * (HW * HW);
    for (int j = tid; j < PAIRS; j += NTHR) {
        float v[4];
#pragma unroll
        for (int k = 0; k < 4; ++k) {
            int i = 2 * j + k;               // column index (may reach TILEN+1)
            int r = i / SW, c = i - r * SW;
            int h = h0 + r - 3, wc = c - 3;
            v[k] = (r < TROWS && (unsigned)h < HW && (unsigned)wc < HW)
                   ? src[h * HW + wc] : 0.0f;
        }
        __half h0v = __float2half(v[0]), h1v = __float2half(v[1]);
        __half h2v = __float2half(v[2]);
        __half d0 = __float2half(v[1] - v[0]);
        __half d1 = __float2half(v[2] - v[1]);
        __half d2 = __float2half(v[3] - v[2]);
        uint2 ea, eb;
        *(__half2*)&ea.x = __halves2half2(h0v, h1v);
        *(__half2*)&ea.y = __halves2half2(d0, d1);
        *(__half2*)&eb.x = __halves2half2(h1v, h2v);
        *(__half2*)&eb.y = __halves2half2(d1, d2);
        EA[j] = ea;
        EB[j] = eb;
    }
    __syncthreads();

    // --- per-bit params (reference-exact index math) -----------------------
    if (tid < BITG) {
        float L = fmaxf(fmaxf(wred[0], wred[1]), fmaxf(wred[2], wred[3]));
        int shift = 3 - (int)ceilf(L);
        int bit = bg * BITG + tid;
        BitH bp;
        {
            float dx = dx1[bit], dy = dy1[bit];
            float fdx = floorf(dx), fdy = floorf(dy);
            int x1 = (int)(L + fdx) + shift;    // trunc toward zero == astype(int32)
            int y1 = (int)(L + fdy) + shift;
            x1 = min(max(x1, 0), 5);            // dynamic_slice start clamp
            y1 = min(max(y1, 0), 5);
            bp.off1 = y1 * SW + x1;
            float fx = dx - fdx, fy = dy - fdy;
            bp.fx1 = __float2half2_rn(fx);
            bp.A1  = __float2half2_rn(0.25f * fy);
            bp.B1  = __float2half2_rn(0.25f * (1.0f - fy));
        }
        {
            float dx = dx2[bit], dy = dy2[bit];
            float fdx = floorf(dx), fdy = floorf(dy);
            int x1 = (int)(L + fdx) + shift;
            int y1 = (int)(L + fdy) + shift;
            x1 = min(max(x1, 0), 5);
            y1 = min(max(y1, 0), 5);
            bp.off2 = y1 * SW + x1;
            float fx = dx - fdx, fy = dy - fdy;
            bp.fx2 = __float2half2_rn(fx);
            bp.A2n = __float2half2_rn(-0.25f * fy);
            bp.B2n = __float2half2_rn(-0.25f * (1.0f - fy));
        }
        bp.c = __float2half2_rn(fmaf(-0.25f, th[bit], 0.125f));
        bp.pad = 0;
        sp[tid] = bp;
    }
    __syncthreads();

    // --- main loop ---------------------------------------------------------
    int cg  = tid % 40;           // column group (4 cols)
    int col = cg * 4;
    int ro0 = (tid / 40) * RR;    // first output row of this thread

    float* outb = out + (((size_t)n * NBITS + bg * BITG) * HW + h0 + ro0) * HW + col;

    for (int b = 0; b < BITG; ++b) {
        BitH bp = sp[b];

        const uint2* q1 = ((bp.off1 & 1) ? EB : EA) + ((bp.off1 + col + ro0 * SW) >> 1);
        const uint2* q2 = ((bp.off2 & 1) ? EB : EA) + ((bp.off2 + col + ro0 * SW) >> 1);

        // all 5 window rows per interp, 2 pair-entries each: batch the LDS.64s
        __half2 z1l[RR + 1], z1h[RR + 1], z2l[RR + 1], z2h[RR + 1];
#pragma unroll
        for (int r = 0; r <= RR; ++r) {
            uint2 ea = q1[r * SW2];
            uint2 eb = q1[r * SW2 + 1];
            z1l[r] = __hfma2(bp.fx1, *(__half2*)&ea.y, *(__half2*)&ea.x);
            z1h[r] = __hfma2(bp.fx1, *(__half2*)&eb.y, *(__half2*)&eb.x);
            uint2 ec = q2[r * SW2];
            uint2 ed = q2[r * SW2 + 1];
            z2l[r] = __hfma2(bp.fx2, *(__half2*)&ec.y, *(__half2*)&ec.x);
            z2h[r] = __hfma2(bp.fx2, *(__half2*)&ed.y, *(__half2*)&ed.x);
        }

        float* op = outb + (size_t)b * (HW * HW);

#pragma unroll
        for (int hh = 0; hh < RR; ++hh) {
            __half2 vl = __hfma2(bp.B1, z1l[hh], bp.c);
            vl = __hfma2(bp.A1,  z1l[hh + 1], vl);
            vl = __hfma2(bp.B2n, z2l[hh], vl);
            vl = hfma2_sat(bp.A2n, z2l[hh + 1], vl);

            __half2 vh = __hfma2(bp.B1, z1h[hh], bp.c);
            vh = __hfma2(bp.A1,  z1h[hh + 1], vh);
            vh = __hfma2(bp.B2n, z2h[hh], vh);
            vh = hfma2_sat(bp.A2n, z2h[hh + 1], vh);

            float2 fl = __half22float2(vl);
            float2 fh = __half22float2(vh);
            float4 f4 = make_float4(fl.x, fl.y, fh.x, fh.y);
            stcs128((float4*)(op + (size_t)hh * HW), f4);
        }
    }
}

// ---------------------------------------------------------------------------
extern "C" void kernel_launch(void* const* d_in, const int* in_sizes, int n_in,
                              void* d_out, int out_size) {
    const float* x   = (const float*)d_in[0];
    const float* dx1 = (const float*)d_in[1];
    const float* dx2 = (const float*)d_in[2];
    const float* dy1 = (const float*)d_in[3];
    const float* dy2 = (const float*)d_in[4];
    const float* th  = (const float*)d_in[5];

    dim3 grid(HW / TH, NBITS / BITG, NIMG);
    fern_main<<<grid, NTHR>>>(x, dx1, dx2, dy1, dy2, th, (float*)d_out);
}

// round 11
// speedup vs baseline: 1.3565x; 1.3565x over previous
#include <cuda_runtime.h>
#include <cuda_fp16.h>

#define HW    160
#define NIMG  32
#define NBITS 128
#define SW    168
#define SW2   (SW / 2)         // 84 pair-entries per row
#define TH    16
#define TROWS 22
#define TILEN (TROWS * SW)     // 3696 column indices
#define PAIRS (TILEN / 2)      // 1848 u64 entries per parity tile
#define BITG  16
#define NTHR  160
#define RR    8                // rows per thread (160 thr = 80 pairs x 2 rgs)

struct __align__(16) BitH {
    __half2 fx1, fx2, B1, A1, B2n, A2n, c;   // 28 B
    int off1, off2;                           // y1*SW + x1 per interp
    int pad;                                  // -> 40 B
};

__device__ __forceinline__ __half2 hfma2_sat(__half2 a, __half2 b, __half2 c) {
    __half2 r;
    asm("fma.rn.sat.f16x2 %0, %1, %2, %3;"
        : "=r"(*(unsigned*)&r)
        : "r"(*(unsigned*)&a), "r"(*(unsigned*)&b), "r"(*(unsigned*)&c));
    return r;
}

__device__ __forceinline__ void stcs64(float* p, float2 v) {
    asm volatile("st.global.cs.v2.f32 [%0], {%1, %2};"
                 :: "l"(p), "f"(v.x), "f"(v.y) : "memory");
}

// ---------------------------------------------------------------------------
// Single fused kernel. Block = (16-row tile, 16-bit group, image), 160 thr =
// 80 column-pairs x 2 row-groups (8 rows each). 2560 blocks: short blocks
// shrink the wave-quantization + drain tail that capped earlier rounds.
// Delta pair-tiles (u64 entries, halves): EA[j]=(p[2j],p[2j+1],d[2j],d[2j+1]),
// EB[j]= same at s=2j+1, d[s]=p[s+1]-p[s] precomputed at fill. Consecutive
// lanes hit consecutive u64 entries -> dense 256B/warp LDS.64 (2 wavefronts).
// Per bit: all 18 window-row loads batch up front (MLP), fold to horizontal
// lerps, then an 8-row pure-FMA combine with streaming (.cs) stores.
// ---------------------------------------------------------------------------
__global__ __launch_bounds__(NTHR) void fern_main(const float* __restrict__ x,
                                                  const float* __restrict__ dx1,
                                                  const float* __restrict__ dx2,
                                                  const float* __restrict__ dy1,
                                                  const float* __restrict__ dy2,
                                                  const float* __restrict__ th,
                                                  float* __restrict__ out) {
    __shared__ __align__(16) uint2 EA[PAIRS];
    __shared__ __align__(16) uint2 EB[PAIRS];
    __shared__ BitH  sp[BITG];
    __shared__ float wred[4];

    int tid = threadIdx.x;
    int h0  = blockIdx.x * TH;
    int bg  = blockIdx.y;
    int n   = blockIdx.z;

    // --- L = max|offset| (warp reductions; identical in every block) -------
    float m = 0.0f;
    if (tid < 128) {
        m = fmaxf(fmaxf(fabsf(dx1[tid]), fabsf(dx2[tid])),
                  fmaxf(fabsf(dy1[tid]), fabsf(dy2[tid])));
    }
#pragma unroll
    for (int o = 16; o; o >>= 1) m = fmaxf(m, __shfl_xor_sync(0xffffffffu, m, o));
    if (tid < 128 && (tid & 31) == 0) wred[tid >> 5] = m;

    // --- fill delta pair-tiles (one thread builds EA[j] and EB[j]) ---------
    const float* src = x + ((size_t)n * 3 + 1) * (HW * HW);
    for (int j = tid; j < PAIRS; j += NTHR) {
        float v[4];
#pragma unroll
        for (int k = 0; k < 4; ++k) {
            int i = 2 * j + k;               // column index (may reach TILEN+1)
            int r = i / SW, c = i - r * SW;
            int h = h0 + r - 3, wc = c - 3;
            v[k] = (r < TROWS && (unsigned)h < HW && (unsigned)wc < HW)
                   ? src[h * HW + wc] : 0.0f;
        }
        __half h0v = __float2half(v[0]), h1v = __float2half(v[1]);
        __half h2v = __float2half(v[2]);
        __half d0 = __float2half(v[1] - v[0]);
        __half d1 = __float2half(v[2] - v[1]);
        __half d2 = __float2half(v[3] - v[2]);
        uint2 ea, eb;
        *(__half2*)&ea.x = __halves2half2(h0v, h1v);
        *(__half2*)&ea.y = __halves2half2(d0, d1);
        *(__half2*)&eb.x = __halves2half2(h1v, h2v);
        *(__half2*)&eb.y = __halves2half2(d1, d2);
        EA[j] = ea;
        EB[j] = eb;
    }
    __syncthreads();

    // --- per-bit params (reference-exact index math) -----------------------
    if (tid < BITG) {
        float L = fmaxf(fmaxf(wred[0], wred[1]), fmaxf(wred[2], wred[3]));
        int shift = 3 - (int)ceilf(L);
        int bit = bg * BITG + tid;
        BitH bp;
        {
            float dx = dx1[bit], dy = dy1[bit];
            float fdx = floorf(dx), fdy = floorf(dy);
            int x1 = (int)(L + fdx) + shift;    // trunc toward zero == astype(int32)
            int y1 = (int)(L + fdy) + shift;
            x1 = min(max(x1, 0), 5);            // dynamic_slice start clamp
            y1 = min(max(y1, 0), 5);
            bp.off1 = y1 * SW + x1;
            float fx = dx - fdx, fy = dy - fdy;
            bp.fx1 = __float2half2_rn(fx);
            bp.A1  = __float2half2_rn(0.25f * fy);
            bp.B1  = __float2half2_rn(0.25f * (1.0f - fy));
        }
        {
            float dx = dx2[bit], dy = dy2[bit];
            float fdx = floorf(dx), fdy = floorf(dy);
            int x1 = (int)(L + fdx) + shift;
            int y1 = (int)(L + fdy) + shift;
            x1 = min(max(x1, 0), 5);
            y1 = min(max(y1, 0), 5);
            bp.off2 = y1 * SW + x1;
            float fx = dx - fdx, fy = dy - fdy;
            bp.fx2 = __float2half2_rn(fx);
            bp.A2n = __float2half2_rn(-0.25f * fy);
            bp.B2n = __float2half2_rn(-0.25f * (1.0f - fy));
        }
        bp.c = __float2half2_rn(fmaf(-0.25f, th[bit], 0.125f));
        bp.pad = 0;
        sp[tid] = bp;
    }
    __syncthreads();

    // --- main loop ---------------------------------------------------------
    int p   = tid % 80;           // column pair
    int wp  = 2 * p;
    int ro0 = (tid / 80) * RR;    // first output row of this thread

    float* outb = out + (((size_t)n * NBITS + bg * BITG) * HW + h0 + ro0) * HW + wp;

    for (int b = 0; b < BITG; ++b) {
        BitH bp = sp[b];

        const uint2* q1 = ((bp.off1 & 1) ? EB : EA) + ((bp.off1 + wp + ro0 * SW) >> 1);
        const uint2* q2 = ((bp.off2 & 1) ? EB : EA) + ((bp.off2 + wp + ro0 * SW) >> 1);

        // all 9 window rows per interp: LDS.64 batch + one HFMA2 each
        __half2 z1[RR + 1], z2[RR + 1];
#pragma unroll
        for (int r = 0; r <= RR; ++r) {
            uint2 e1 = q1[r * SW2];
            uint2 e2 = q2[r * SW2];
            z1[r] = __hfma2(bp.fx1, *(__half2*)&e1.y, *(__half2*)&e1.x);
            z2[r] = __hfma2(bp.fx2, *(__half2*)&e2.y, *(__half2*)&e2.x);
        }

        float* op = outb + (size_t)b * (HW * HW);

#pragma unroll
        for (int hh = 0; hh < RR; ++hh) {
            __half2 v = __hfma2(bp.B1, z1[hh], bp.c);
            v = __hfma2(bp.A1,  z1[hh + 1], v);
            v = __hfma2(bp.B2n, z2[hh], v);
            v = hfma2_sat(bp.A2n, z2[hh + 1], v);

            stcs64(op + (size_t)hh * HW, __half22float2(v));
        }
    }
}

// ---------------------------------------------------------------------------
extern "C" void kernel_launch(void* const* d_in, const int* in_sizes, int n_in,
                              void* d_out, int out_size) {
    const float* x   = (const float*)d_in[0];
    const float* dx1 = (const float*)d_in[1];
    const float* dx2 = (const float*)d_in[2];
    const float* dy1 = (const float*)d_in[3];
    const float* dy2 = (const float*)d_in[4];
    const float* th  = (const float*)d_in[5];

    dim3 grid(HW / TH, NBITS / BITG, NIMG);
    fern_main<<<grid, NTHR>>>(x, dx1, dx2, dy1, dy2, th, (float*)d_out);
}